// round 4
// baseline (speedup 1.0000x reference)
#include <cuda_runtime.h>

typedef unsigned long long ull;

#define HH 512
#define WW 512
#define BB 16
#define RPB 4
#define GRIDX (HH / RPB)      // 128
#define NBLK  (GRIDX * BB)    // 2048
#define NTHR  128
#define FULLM 0xffffffffu

__device__ float    g_part[NBLK];
__device__ unsigned g_cnt = 0;

// ---- packed f32x2 helpers (sm_103a FFMA2 path, PTX-only) ----
__device__ __forceinline__ ull pk(float lo, float hi) {
    ull r; asm("mov.b64 %0,{%1,%2};" : "=l"(r) : "f"(lo), "f"(hi)); return r;
}
__device__ __forceinline__ void upk(ull v, float& lo, float& hi) {
    asm("mov.b64 {%0,%1},%2;" : "=f"(lo), "=f"(hi) : "l"(v));
}
__device__ __forceinline__ ull sub2(ull a, ull b){ ull r; asm("sub.rn.f32x2 %0,%1,%2;":"=l"(r):"l"(a),"l"(b)); return r; }
__device__ __forceinline__ ull add2(ull a, ull b){ ull r; asm("add.rn.f32x2 %0,%1,%2;":"=l"(r):"l"(a),"l"(b)); return r; }
__device__ __forceinline__ ull mul2(ull a, ull b){ ull r; asm("mul.rn.f32x2 %0,%1,%2;":"=l"(r):"l"(a),"l"(b)); return r; }
__device__ __forceinline__ ull fma2(ull a, ull b, ull c){ ull r; asm("fma.rn.f32x2 %0,%1,%2,%3;":"=l"(r):"l"(a),"l"(b),"l"(c)); return r; }
__device__ __forceinline__ float ex2f(float x){ float r; asm("ex2.approx.f32 %0,%1;":"=f"(r):"f"(x)); return r; }

// packed shift-term for 2 pixels:
//   t = (ex2(d2 * C2) * wxy - eps) * (ya-yb)^2 * [mask]
// C2 = -log2(e)/(2*sigma^2) folded so ex2 is used directly.
template<bool MASK>
__device__ __forceinline__ void pterm(ull& acc,
        ull a0, ull a1, ull a2, ull b0, ull b1, ull b2,
        ull ya, ull yb, ull wxy, ull mask, ull c2, ull negeps)
{
    ull d0 = sub2(a0, b0), d1 = sub2(a1, b1), d2 = sub2(a2, b2);
    ull s  = mul2(d0, d0);
    s = fma2(d1, d1, s);
    s = fma2(d2, d2, s);
    s = mul2(s, c2);
    float s0, s1; upk(s, s0, s1);
    ull e  = pk(ex2f(s0), ex2f(s1));
    ull m  = fma2(e, wxy, negeps);     // e*wxy - 0.01
    ull dy = sub2(ya, yb);
    ull t  = mul2(m, mul2(dy, dy));
    if (MASK) t = mul2(t, mask);
    acc = add2(acc, t);
}

// packed pairs for one array on one row (4 px/thread + halos)
struct PR { ull c0, c1, r0, r1, l0; };
// c0=(x0,x1) c1=(x2,x3) : aligned center pairs
// r0=(x1,x2) r1=(x3,xR) : +1-shift neighbors of c0,c1
// l0=(xL,x0)            : -1-shift neighbor of c0   (c1's is r0)
struct Row4 { PR y, a, b, c; };

__device__ __forceinline__ Row4 loadrow(const float* __restrict__ Y,
                                        const float* __restrict__ A,
                                        const float* __restrict__ Bp,
                                        const float* __restrict__ Cp,
                                        int off, int lane, bool hasR, bool hasL)
{
    Row4 R;
    float4 t; float xr, xl;
#define LDROW(P, F)                                               \
    t  = *(const float4*)(P + off);                               \
    xr = __shfl_down_sync(FULLM, t.x, 1);                         \
    if (lane == 31) xr = hasR ? __ldg(P + off + 4) : 0.0f;        \
    xl = __shfl_up_sync(FULLM, t.w, 1);                           \
    if (lane == 0)  xl = hasL ? __ldg(P + off - 1) : 0.0f;        \
    R.F.c0 = pk(t.x, t.y); R.F.c1 = pk(t.z, t.w);                 \
    R.F.r0 = pk(t.y, t.z); R.F.r1 = pk(t.w, xr);                  \
    R.F.l0 = pk(xl, t.x);
    LDROW(Y,  y)
    LDROW(A,  a)
    LDROW(Bp, b)
    LDROW(Cp, c)
#undef LDROW
    return R;
}

__global__ void __launch_bounds__(NTHR, 6)
crf_loss_kernel(const float* __restrict__ ypr,
                const float* __restrict__ img,
                const int*   __restrict__ icls,
                float* __restrict__ out)
{
    const int tid  = threadIdx.x;
    const int lane = tid & 31;
    const int bx   = blockIdx.x;
    const int b    = blockIdx.y;
    const int bid  = b * GRIDX + bx;
    const int w0   = tid << 2;              // 4 px/thread, 128 thr = full row
    const int r0   = bx * RPB;

    __shared__ float sm[NTHR / 32];
    __shared__ bool  s_last;

    float blocksum = 0.0f;                  // valid on tid 0

    if (icls[b] != 0) {
        const float* Y  = ypr + (size_t)(2 * b + 1) * (HH * WW);
        const float* I0 = img + (size_t)(3 * b)     * (HH * WW);
        const float* I1 = I0 + HH * WW;
        const float* I2 = I1 + HH * WW;

        const bool hasR = (w0 + 4 < WW);    // false only tid 127
        const bool hasL = (w0 > 0);         // false only tid 0

        const ull C2  = pk(-32.05988979753252f, -32.05988979753252f); // -log2e/(2*0.15^2)
        const ull NE2 = pk(-0.01f, -0.01f);
        const ull W1  = pk(0.60653065971263342f, 0.60653065971263342f); // exp(-0.5)
        const ull W2  = pk(0.36787944117144233f, 0.36787944117144233f); // exp(-1.0)
        const ull MR  = pk(1.0f, hasR ? 1.0f : 0.0f);
        const ull ML  = pk(hasL ? 1.0f : 0.0f, 1.0f);

        ull acc = 0;  // packed (+0, +0)

        // horizontal shift (0,1) within one row: self centers vs right pairs
#define HORIZ(RW)                                                              \
        pterm<false>(acc, RW.a.c0, RW.b.c0, RW.c.c0,                           \
                          RW.a.r0, RW.b.r0, RW.c.r0, RW.y.c0, RW.y.r0,         \
                          W1, MR, C2, NE2);                                    \
        pterm<true >(acc, RW.a.c1, RW.b.c1, RW.c.c1,                           \
                          RW.a.r1, RW.b.r1, RW.c.r1, RW.y.c1, RW.y.r1,         \
                          W1, MR, C2, NE2);

        // prologue: row r0
        Row4 cur = loadrow(Y, I0, I1, I2, r0 * WW + w0, lane, hasR, hasL);
        HORIZ(cur)
        ull ya0 = cur.y.c0, ya1 = cur.y.c1;
        ull aa0 = cur.a.c0, aa1 = cur.a.c1;
        ull ba0 = cur.b.c0, ba1 = cur.b.c1;
        ull ca0 = cur.c.c0, ca1 = cur.c.c1;

#pragma unroll
        for (int rr = 0; rr < RPB; rr++) {
            const int r = r0 + rr + 1;
            if (r < HH) {                   // uniform; false only last strip's last iter
                Row4 nx = loadrow(Y, I0, I1, I2, r * WW + w0, lane, hasR, hasL);
                if (rr < RPB - 1) { HORIZ(nx) }   // row r's horizontal owned by this strip

                // shift (1,0): cur centers vs nx centers (no mask)
                pterm<false>(acc, aa0, ba0, ca0, nx.a.c0, nx.b.c0, nx.c.c0,
                             ya0, nx.y.c0, W1, MR, C2, NE2);
                pterm<false>(acc, aa1, ba1, ca1, nx.a.c1, nx.b.c1, nx.c.c1,
                             ya1, nx.y.c1, W1, MR, C2, NE2);
                // shift (1,1): cur centers vs nx right pairs
                pterm<false>(acc, aa0, ba0, ca0, nx.a.r0, nx.b.r0, nx.c.r0,
                             ya0, nx.y.r0, W2, MR, C2, NE2);
                pterm<true >(acc, aa1, ba1, ca1, nx.a.r1, nx.b.r1, nx.c.r1,
                             ya1, nx.y.r1, W2, MR, C2, NE2);
                // shift (1,-1): cur centers vs nx left pairs (l1 == r0)
                pterm<true >(acc, aa0, ba0, ca0, nx.a.l0, nx.b.l0, nx.c.l0,
                             ya0, nx.y.l0, W2, ML, C2, NE2);
                pterm<false>(acc, aa1, ba1, ca1, nx.a.r0, nx.b.r0, nx.c.r0,
                             ya1, nx.y.r0, W2, MR, C2, NE2);

                ya0 = nx.y.c0; ya1 = nx.y.c1;
                aa0 = nx.a.c0; aa1 = nx.a.c1;
                ba0 = nx.b.c0; ba1 = nx.b.c1;
                ca0 = nx.c.c0; ca1 = nx.c.c1;
            }
        }
#undef HORIZ

        float aL0, aH0; upk(acc, aL0, aH0);
        float v = aL0 + aH0;
#pragma unroll
        for (int o = 16; o > 0; o >>= 1)
            v += __shfl_down_sync(FULLM, v, o);
        if (lane == 0) sm[tid >> 5] = v;
        __syncthreads();
        if (tid == 0)
            blocksum = sm[0] + sm[1] + sm[2] + sm[3];
    }

    // ---- single-kernel deterministic global reduction ----
    if (tid == 0) {
        g_part[bid] = blocksum;
        __threadfence();
        unsigned old = atomicInc(&g_cnt, NBLK - 1u);   // wraps to 0 each launch
        s_last = (old == NBLK - 1u);
    }
    __syncthreads();

    if (s_last) {
        float v = 0.0f;
        for (int i = tid; i < NBLK; i += NTHR)
            v += ((volatile float*)g_part)[i];
#pragma unroll
        for (int o = 16; o > 0; o >>= 1)
            v += __shfl_down_sync(FULLM, v, o);
        if (lane == 0) sm[tid >> 5] = v;
        __syncthreads();
        if (tid == 0) {
            float s = sm[0] + sm[1] + sm[2] + sm[3];
            const float SCALE = 1.0f / 16777216.0f;    // 1/(H*W*B*4), WEIGHT=1
            out[0] = s * SCALE;
        }
    }
}

extern "C" void kernel_launch(void* const* d_in, const int* in_sizes, int n_in,
                              void* d_out, int out_size) {
    const float* ypr  = (const float*)d_in[0];   // y_pr  (16,2,512,512)
    // d_in[1] = y_gt (unused by the reference)
    const float* img  = (const float*)d_in[2];   // image (16,3,512,512)
    const int*   icls = (const int*)d_in[3];     // image_class (16,)
    float* out = (float*)d_out;

    dim3 grid(GRIDX, BB);
    crf_loss_kernel<<<grid, NTHR>>>(ypr, img, icls, out);
}

// round 5
// speedup vs baseline: 1.0017x; 1.0017x over previous
#include <cuda_runtime.h>

#define HH 512
#define WW 512
#define BB 16
#define RPB 8
#define GRIDX (HH / RPB)      // 64
#define NBLK  (GRIDX * BB)    // 1024
#define NTHR  128
#define FULLM 0xffffffffu

__device__ float    g_part[NBLK];
__device__ unsigned g_cnt = 0;

__device__ __forceinline__ float shift_term(float a0, float a1, float a2,
                                            float b0, float b1, float b2,
                                            float ya, float yb, float wxy) {
    const float INV2S2 = 22.222222222222221f;   // 1/(2*0.15^2)
    float dx0 = a0 - b0, dx1 = a1 - b1, dx2 = a2 - b2;
    float d2 = dx0 * dx0 + dx1 * dx1 + dx2 * dx2;
    float m = __expf(-d2 * INV2S2) * wxy - 0.01f;  // SUB_EPS
    float dy = ya - yb;
    return m * dy * dy;
}

__global__ void __launch_bounds__(NTHR, 8)
crf_loss_kernel(const float* __restrict__ ypr,
                const float* __restrict__ img,
                const int*   __restrict__ icls,
                float* __restrict__ out)
{
    const int tid  = threadIdx.x;
    const int lane = tid & 31;
    const int bx   = blockIdx.x;
    const int b    = blockIdx.y;
    const int bid  = b * GRIDX + bx;
    const int w0   = tid << 2;                 // 4 px/thread, 128 thr = full row
    const int r0   = bx * RPB;

    __shared__ float sm[NTHR / 32];
    __shared__ bool  s_last;

    float blocksum = 0.0f;                     // valid on tid 0

    if (icls[b] != 0) {
        const float* Y  = ypr + (size_t)(2 * b + 1) * (HH * WW);
        const float* I0 = img + (size_t)(3 * b)     * (HH * WW);
        const float* I1 = I0 + HH * WW;
        const float* I2 = I1 + HH * WW;

        const bool lastLane  = (lane == 31);
        const bool firstLane = (lane == 0);
        const bool hasR = (w0 + 4 < WW);       // false only tid 127
        const bool hasL = (w0 > 0);            // false only tid 0

        const float WXY1 = 0.60653065971263342f;  // exp(-0.5)
        const float WXY2 = 0.36787944117144233f;  // exp(-1.0)

        // ---- current row (r0) + right halo ----
        float cy[4], ca[4], cb[4], cc[4];
        float cyR, caR, cbR, ccR;
        {
            const int off = r0 * WW + w0;
            float4 t;
            t = *(const float4*)(Y  + off); cy[0]=t.x; cy[1]=t.y; cy[2]=t.z; cy[3]=t.w;
            t = *(const float4*)(I0 + off); ca[0]=t.x; ca[1]=t.y; ca[2]=t.z; ca[3]=t.w;
            t = *(const float4*)(I1 + off); cb[0]=t.x; cb[1]=t.y; cb[2]=t.z; cb[3]=t.w;
            t = *(const float4*)(I2 + off); cc[0]=t.x; cc[1]=t.y; cc[2]=t.z; cc[3]=t.w;
            cyR = __shfl_down_sync(FULLM, cy[0], 1);
            caR = __shfl_down_sync(FULLM, ca[0], 1);
            cbR = __shfl_down_sync(FULLM, cb[0], 1);
            ccR = __shfl_down_sync(FULLM, cc[0], 1);
            if (lastLane) {
                cyR = hasR ? Y [off + 4] : 0.0f;
                caR = hasR ? I0[off + 4] : 0.0f;
                cbR = hasR ? I1[off + 4] : 0.0f;
                ccR = hasR ? I2[off + 4] : 0.0f;
            }
        }

        float acc = 0.0f;

#pragma unroll
        for (int rr = 0; rr < RPB; rr++) {
            const int r = r0 + rr;
            const bool haveDown = (r + 1 < HH);   // uniform across block

            // ---- load next row (r+1) + halos ----
            float ny[4], na[4], nb[4], nc[4];
            float nyR = 0.f, naR = 0.f, nbR = 0.f, ncR = 0.f;
            float nyL = 0.f, naL = 0.f, nbL = 0.f, ncL = 0.f;
            if (haveDown) {
                const int off = (r + 1) * WW + w0;
                float4 t;
                t = *(const float4*)(Y  + off); ny[0]=t.x; ny[1]=t.y; ny[2]=t.z; ny[3]=t.w;
                t = *(const float4*)(I0 + off); na[0]=t.x; na[1]=t.y; na[2]=t.z; na[3]=t.w;
                t = *(const float4*)(I1 + off); nb[0]=t.x; nb[1]=t.y; nb[2]=t.z; nb[3]=t.w;
                t = *(const float4*)(I2 + off); nc[0]=t.x; nc[1]=t.y; nc[2]=t.z; nc[3]=t.w;

                nyR = __shfl_down_sync(FULLM, ny[0], 1);
                naR = __shfl_down_sync(FULLM, na[0], 1);
                nbR = __shfl_down_sync(FULLM, nb[0], 1);
                ncR = __shfl_down_sync(FULLM, nc[0], 1);
                if (lastLane) {
                    nyR = hasR ? Y [off + 4] : 0.0f;
                    naR = hasR ? I0[off + 4] : 0.0f;
                    nbR = hasR ? I1[off + 4] : 0.0f;
                    ncR = hasR ? I2[off + 4] : 0.0f;
                }
                nyL = __shfl_up_sync(FULLM, ny[3], 1);
                naL = __shfl_up_sync(FULLM, na[3], 1);
                nbL = __shfl_up_sync(FULLM, nb[3], 1);
                ncL = __shfl_up_sync(FULLM, nc[3], 1);
                if (firstLane) {
                    nyL = hasL ? Y [off - 1] : 0.0f;
                    naL = hasL ? I0[off - 1] : 0.0f;
                    nbL = hasL ? I1[off - 1] : 0.0f;
                    ncL = hasL ? I2[off - 1] : 0.0f;
                }
            } else {
#pragma unroll
                for (int k = 0; k < 4; k++) { ny[k]=0.f; na[k]=0.f; nb[k]=0.f; nc[k]=0.f; }
            }

            // ---- horizontal shift (0,1) on current row ----
#pragma unroll
            for (int k = 0; k < 3; k++)
                acc += shift_term(ca[k], cb[k], cc[k],
                                  ca[k+1], cb[k+1], cc[k+1],
                                  cy[k], cy[k+1], WXY1);
            if (hasR)
                acc += shift_term(ca[3], cb[3], cc[3], caR, cbR, ccR,
                                  cy[3], cyR, WXY1);

            if (haveDown) {
                // shift (1,0)
#pragma unroll
                for (int k = 0; k < 4; k++)
                    acc += shift_term(ca[k], cb[k], cc[k],
                                      na[k], nb[k], nc[k],
                                      cy[k], ny[k], WXY1);
                // shift (1,1)
#pragma unroll
                for (int k = 0; k < 3; k++)
                    acc += shift_term(ca[k], cb[k], cc[k],
                                      na[k+1], nb[k+1], nc[k+1],
                                      cy[k], ny[k+1], WXY2);
                if (hasR)
                    acc += shift_term(ca[3], cb[3], cc[3], naR, nbR, ncR,
                                      cy[3], nyR, WXY2);
                // shift (1,-1)
#pragma unroll
                for (int k = 1; k < 4; k++)
                    acc += shift_term(ca[k], cb[k], cc[k],
                                      na[k-1], nb[k-1], nc[k-1],
                                      cy[k], ny[k-1], WXY2);
                if (hasL)
                    acc += shift_term(ca[0], cb[0], cc[0], naL, nbL, ncL,
                                      cy[0], nyL, WXY2);
            }

            // ---- roll ----
#pragma unroll
            for (int k = 0; k < 4; k++) { cy[k]=ny[k]; ca[k]=na[k]; cb[k]=nb[k]; cc[k]=nc[k]; }
            cyR = nyR; caR = naR; cbR = nbR; ccR = ncR;
        }

        // ---- block reduction ----
#pragma unroll
        for (int o = 16; o > 0; o >>= 1)
            acc += __shfl_down_sync(FULLM, acc, o);
        if (lane == 0) sm[tid >> 5] = acc;
        __syncthreads();
        if (tid == 0)
            blocksum = sm[0] + sm[1] + sm[2] + sm[3];
    }

    // ---- single-kernel deterministic global reduction ----
    if (tid == 0) {
        g_part[bid] = blocksum;
        __threadfence();
        unsigned old = atomicInc(&g_cnt, NBLK - 1u);   // wraps to 0 every launch
        s_last = (old == NBLK - 1u);
    }
    __syncthreads();

    if (s_last) {
        float v = 0.0f;
        for (int i = tid; i < NBLK; i += NTHR)
            v += ((volatile float*)g_part)[i];
#pragma unroll
        for (int o = 16; o > 0; o >>= 1)
            v += __shfl_down_sync(FULLM, v, o);
        if (lane == 0) sm[tid >> 5] = v;
        __syncthreads();
        if (tid == 0) {
            float s = sm[0] + sm[1] + sm[2] + sm[3];
            const float SCALE = 1.0f / 16777216.0f;    // 1/(H*W*B*4), WEIGHT=1
            out[0] = s * SCALE;
        }
    }
}

extern "C" void kernel_launch(void* const* d_in, const int* in_sizes, int n_in,
                              void* d_out, int out_size) {
    const float* ypr  = (const float*)d_in[0];   // y_pr  (16,2,512,512)
    // d_in[1] = y_gt (unused by the reference)
    const float* img  = (const float*)d_in[2];   // image (16,3,512,512)
    const int*   icls = (const int*)d_in[3];     // image_class (16,)
    float* out = (float*)d_out;

    dim3 grid(GRIDX, BB);
    crf_loss_kernel<<<grid, NTHR>>>(ypr, img, icls, out);
}